// round 1
// baseline (speedup 1.0000x reference)
#include <cuda_runtime.h>

#define NB 16     // batch
#define DD 128    // feature dim
#define NN 16     // nodes
#define EE 120    // candidate edges = 16*15/2

// Scratch for the per-batch bilinear forms T1, T2 (16x16 each)
__device__ float g_T[NB][2][NN][NN];

// Kernel 1: T[m][x][y] = sum_{i,j} Fs[i][x] * relu(lam_m[i][j] + lam_m[j][i]) * Ft[j][y]
// grid (2 matrices, 16 batches), 256 threads, dynamic smem:
//   sW [128*128] + sFs [128*16] + sFt [128*16] + sV [128*16]
__global__ void k_T(const float* __restrict__ F_src,
                    const float* __restrict__ F_tgt,
                    const float* __restrict__ lam1,
                    const float* __restrict__ lam2) {
    extern __shared__ float sm[];
    float* sW  = sm;                  // 16384 floats
    float* sFs = sW + DD * DD;        // 2048
    float* sFt = sFs + DD * NN;       // 2048
    float* sV  = sFt + DD * NN;       // 2048

    const int m = blockIdx.x;
    const int b = blockIdx.y;
    const int t = threadIdx.x;
    const float* __restrict__ lam = (m == 0) ? lam1 : lam2;

    // Build W = relu(lam + lam^T) into shared (64 entries / thread)
    #pragma unroll
    for (int k = 0; k < 64; k++) {
        int idx = t + k * 256;
        int i = idx >> 7, j = idx & 127;
        float v = lam[i * DD + j] + lam[j * DD + i];
        sW[idx] = v > 0.f ? v : 0.f;
    }
    // Stage F tiles (coalesced)
    const float* __restrict__ Fs = F_src + b * DD * NN;
    const float* __restrict__ Ft = F_tgt + b * DD * NN;
    #pragma unroll
    for (int k = 0; k < 8; k++) {
        sFs[t + k * 256] = Fs[t + k * 256];
        sFt[t + k * 256] = Ft[t + k * 256];
    }
    __syncthreads();

    // V[i][y] = sum_j W[i][j] * Ft[j][y]
    // thread t handles y = t&15, i in {t>>4 + 16k}, k<8
    const int y  = t & 15;
    const int i0 = t >> 4;
    float acc[8];
    #pragma unroll
    for (int k = 0; k < 8; k++) acc[k] = 0.f;

    for (int j = 0; j < DD; j += 4) {
        float f0 = sFt[(j + 0) * NN + y];
        float f1 = sFt[(j + 1) * NN + y];
        float f2 = sFt[(j + 2) * NN + y];
        float f3 = sFt[(j + 3) * NN + y];
        #pragma unroll
        for (int k = 0; k < 8; k++) {
            float4 w = *reinterpret_cast<const float4*>(&sW[(i0 + 16 * k) * DD + j]);
            acc[k] += w.x * f0 + w.y * f1 + w.z * f2 + w.w * f3;
        }
    }
    #pragma unroll
    for (int k = 0; k < 8; k++)
        sV[(i0 + 16 * k) * NN + y] = acc[k];
    __syncthreads();

    // T[x][y] = sum_i Fs[i][x] * V[i][y]   (x = t>>4, y = t&15)
    const int x = t >> 4;
    float tv = 0.f;
    #pragma unroll 4
    for (int i = 0; i < DD; i++)
        tv += sFs[i * NN + x] * sV[i * NN + y];
    g_T[b][m][x][y] = tv;
}

// Kernel 2: assemble M[b, i2*16+i1, j2*16+j1]
//   off-diag: (i2<j2 && i1<j1 && B[e1] && B[e2]) ? T1[i2,i1]+T2[i2,j1]+T2[j2,i1]+T1[j2,j1] : 0
//   diag (i==j): += sum_d U_src[b,d,i2] * U_tgt[b,d,i1]
// grid (16 i2, 16 b), 256 threads = j
__global__ void k_asm(const int* __restrict__ A_src,
                      const int* __restrict__ A_tgt,
                      const float* __restrict__ U_src,
                      const float* __restrict__ U_tgt,
                      float* __restrict__ out) {
    __shared__ float T1[256];
    __shared__ float T2[256];
    __shared__ float Mp[16];
    __shared__ unsigned char Bm[EE];

    const int i2 = blockIdx.x;
    const int b  = blockIdx.y;
    const int t  = threadIdx.x;

    T1[t] = (&g_T[b][0][0][0])[t];
    T2[t] = (&g_T[b][1][0][0])[t];
    if (t < EE)
        Bm[t] = (A_src[b * EE + t] > 0) && (A_tgt[b * EE + t] > 0);
    if (t < 16) {
        // Mp[m] = sum_d U_src[b,d,i2] * U_tgt[b,d,m]
        float s = 0.f;
        #pragma unroll
        for (int d = 0; d < 16; d++)
            s += U_src[(b * 16 + d) * 16 + i2] * U_tgt[(b * 16 + d) * 16 + t];
        Mp[t] = s;
    }
    __syncthreads();

    const int j  = t;
    const int j2 = j >> 4;
    const int j1 = j & 15;

    const bool c2 = (i2 < j2);
    const int  e2 = c2 ? (i2 * (31 - i2)) / 2 + (j2 - i2 - 1) : 0;
    const bool b2 = c2 && (Bm[e2] != 0);

    const float t2_i2_j1 = T2[i2 * 16 + j1];
    const float t1_j2_j1 = T1[j2 * 16 + j1];

    float* __restrict__ o = out + ((size_t)b * 256 + i2 * 16) * 256 + j;

    #pragma unroll
    for (int i1 = 0; i1 < 16; i1++) {
        float v = 0.f;
        if (b2 && i1 < j1) {
            int e1 = (i1 * (31 - i1)) / 2 + (j1 - i1 - 1);
            if (Bm[e1])
                v = T1[i2 * 16 + i1] + t2_i2_j1 + T2[j2 * 16 + i1] + t1_j2_j1;
        }
        if (j2 == i2 && j1 == i1) v += Mp[j1];
        o[i1 * 256] = v;
    }
}

static const int K1_SMEM = (DD * DD + 3 * DD * NN) * (int)sizeof(float);  // 90112 B

extern "C" void kernel_launch(void* const* d_in, const int* in_sizes, int n_in,
                              void* d_out, int out_size) {
    const int*   A_src = (const int*)d_in[0];
    const int*   A_tgt = (const int*)d_in[1];
    const float* F_src = (const float*)d_in[2];
    const float* F_tgt = (const float*)d_in[3];
    const float* U_src = (const float*)d_in[4];
    const float* U_tgt = (const float*)d_in[5];
    const float* lam1  = (const float*)d_in[6];
    const float* lam2  = (const float*)d_in[7];
    float* out = (float*)d_out;

    cudaFuncSetAttribute(k_T, cudaFuncAttributeMaxDynamicSharedMemorySize, K1_SMEM);

    k_T<<<dim3(2, 16), 256, K1_SMEM>>>(F_src, F_tgt, lam1, lam2);
    k_asm<<<dim3(16, 16), 256>>>(A_src, A_tgt, U_src, U_tgt, out);
}

// round 3
// speedup vs baseline: 1.8175x; 1.8175x over previous
#include <cuda_runtime.h>

#define NB 16     // batch
#define DD 128    // feature dim
#define NN 16     // nodes
#define EE 120    // candidate edges = 16*15/2
#define NS 4      // i-splits of the K reduction in k_T
#define IR 32     // rows per split (DD/NS)
#define WP 132    // padded W row stride (floats) — kills bank conflicts

// Partial bilinear forms: g_Tp[m][b][split][x*16+y]; k_asm sums over split.
__device__ float g_Tp[2][NB][NS][NN * NN];

// ---------------------------------------------------------------------------
// k_T: per (split s, batch b, matrix m) block computes V rows [32s,32s+32) of
//      V = relu(lam+lam^T) * Ft   and the partial  T_s = Fs_rows^T * V_rows.
// grid (4, 16, 2) = 128 blocks, 256 threads.
// ---------------------------------------------------------------------------
__global__ __launch_bounds__(256, 1)
void k_T(const float* __restrict__ F_src,
         const float* __restrict__ F_tgt,
         const float* __restrict__ lam1,
         const float* __restrict__ lam2) {
    __shared__ float sW[IR * WP];      // 32 x 128 (padded stride 132)
    __shared__ float sFt[DD * NN];     // 128 x 16
    __shared__ float sFs[IR * NN];     // 32 x 16
    __shared__ float sV[IR * NN];      // 32 x 16

    const int s = blockIdx.x;
    const int b = blockIdx.y;
    const int m = blockIdx.z;
    const int t = threadIdx.x;
    const float* __restrict__ lam = (m == 0) ? lam1 : lam2;
    const int ibase = s * IR;

    // W rows [ibase, ibase+32): relu(lam[i][j] + lam[j][i])
    #pragma unroll
    for (int k = 0; k < 16; k++) {
        int idx = t + k * 256;             // 4096 entries
        int il = idx >> 7, j = idx & 127;
        int gi = ibase + il;
        float v = lam[gi * DD + j] + lam[j * DD + gi];
        sW[il * WP + j] = v > 0.f ? v : 0.f;
    }
    // Ft full tile (coalesced)
    const float* __restrict__ Ft = F_tgt + b * DD * NN;
    #pragma unroll
    for (int k = 0; k < 8; k++)
        sFt[t + k * 256] = Ft[t + k * 256];
    // Fs rows slice: 512 floats, 256 threads -> 2 per thread  (BUGFIX)
    {
        const float* __restrict__ Fs = F_src + b * DD * NN + ibase * NN;
        sFs[t]       = Fs[t];
        sFs[t + 256] = Fs[t + 256];
    }
    __syncthreads();

    // V rows: thread t -> y = t&15, il in {t>>4, t>>4 + 16}
    const int y  = t & 15;
    const int il = t >> 4;
    float a0 = 0.f, a1 = 0.f;
    #pragma unroll 8
    for (int j = 0; j < DD; j += 4) {
        float f0 = sFt[(j + 0) * NN + y];
        float f1 = sFt[(j + 1) * NN + y];
        float f2 = sFt[(j + 2) * NN + y];
        float f3 = sFt[(j + 3) * NN + y];
        float4 w0 = *reinterpret_cast<const float4*>(&sW[il * WP + j]);
        float4 w1 = *reinterpret_cast<const float4*>(&sW[(il + 16) * WP + j]);
        a0 += w0.x * f0 + w0.y * f1 + w0.z * f2 + w0.w * f3;
        a1 += w1.x * f0 + w1.y * f1 + w1.z * f2 + w1.w * f3;
    }
    sV[il * NN + y] = a0;
    sV[(il + 16) * NN + y] = a1;
    __syncthreads();

    // Partial T over this i-slice: (x = t>>4, y = t&15)
    const int x = t >> 4;
    float tv = 0.f;
    #pragma unroll
    for (int i = 0; i < IR; i++)
        tv += sFs[i * NN + x] * sV[i * NN + y];
    g_Tp[m][b][s][x * NN + y] = tv;
}

// ---------------------------------------------------------------------------
// k_asm: assemble M[b, i2*16+i1, j2*16+j1]
//   off-diag: (i2<j2 && i1<j1 && B[e(i1,j1)] && B[e(i2,j2)])
//               ? T1[i2,i1] + T2[i2,j1] + T2[j2,i1] + T1[j2,j1] : 0
//   diag (i==j): += sum_d U_src[b,d,i2] * U_tgt[b,d,i1]
// grid (16 i2, 16 b), 256 threads. Each thread writes a 4x4 tile via 4 STG.128.
// ---------------------------------------------------------------------------
__global__ __launch_bounds__(256, 4)
void k_asm(const int* __restrict__ A_src,
           const int* __restrict__ A_tgt,
           const float* __restrict__ U_src,
           const float* __restrict__ U_tgt,
           float* __restrict__ out) {
    __shared__ float T1[256];
    __shared__ float T2[256];
    __shared__ float Mp[16];
    __shared__ unsigned char Bm[EE + 8];

    const int i2 = blockIdx.x;
    const int b  = blockIdx.y;
    const int t  = threadIdx.x;

    // Sum the 4 K-split partials
    {
        float s1 = 0.f, s2 = 0.f;
        #pragma unroll
        for (int s = 0; s < NS; s++) {
            s1 += g_Tp[0][b][s][t];
            s2 += g_Tp[1][b][s][t];
        }
        T1[t] = s1;
        T2[t] = s2;
    }
    if (t < EE)
        Bm[t] = (A_src[b * EE + t] > 0) && (A_tgt[b * EE + t] > 0);
    if (t < 16) {
        float s = 0.f;
        #pragma unroll
        for (int d = 0; d < 16; d++)
            s += U_src[(b * 16 + d) * 16 + i2] * U_tgt[(b * 16 + d) * 16 + t];
        Mp[t] = s;
    }
    __syncthreads();

    // thread -> 4 consecutive j (one float4) x 4 i1 values
    const int j4  = t & 63;          // j = 4*j4 .. 4*j4+3
    const int i1g = t >> 6;          // i1 = 4*i1g .. 4*i1g+3
    const int j2  = j4 >> 2;
    const int j1b = (j4 & 3) * 4;

    const bool c2 = (i2 < j2);
    const int  e2 = c2 ? (i2 * (31 - i2)) / 2 + (j2 - i2 - 1) : 0;
    const bool b2 = c2 && (Bm[e2] != 0);
    const bool dg = (j2 == i2);

    // Hoisted row values
    float t2i[4], t1j[4];            // T2[i2, j1], T1[j2, j1] per j1 lane
    #pragma unroll
    for (int l = 0; l < 4; l++) {
        t2i[l] = T2[i2 * 16 + j1b + l];
        t1j[l] = T1[j2 * 16 + j1b + l];
    }

    float* __restrict__ o =
        out + ((size_t)(b * 256 + i2 * 16 + i1g * 4)) * 256 + j2 * 16 + j1b;

    #pragma unroll
    for (int q = 0; q < 4; q++) {
        const int i1 = i1g * 4 + q;
        const float t1i = T1[i2 * 16 + i1];   // T1[i2, i1]
        const float t2j = T2[j2 * 16 + i1];   // T2[j2, i1]
        float4 v;
        float* vp = &v.x;
        #pragma unroll
        for (int l = 0; l < 4; l++) {
            const int j1 = j1b + l;
            float val = 0.f;
            if (b2 && i1 < j1) {
                int e1 = (i1 * (31 - i1)) / 2 + (j1 - i1 - 1);
                if (Bm[e1])
                    val = t1i + t2i[l] + t2j + t1j[l];
            }
            if (dg && j1 == i1) val += Mp[i1];
            vp[l] = val;
        }
        *reinterpret_cast<float4*>(o + (size_t)q * 256) = v;
    }
}

extern "C" void kernel_launch(void* const* d_in, const int* in_sizes, int n_in,
                              void* d_out, int out_size) {
    const int*   A_src = (const int*)d_in[0];
    const int*   A_tgt = (const int*)d_in[1];
    const float* F_src = (const float*)d_in[2];
    const float* F_tgt = (const float*)d_in[3];
    const float* U_src = (const float*)d_in[4];
    const float* U_tgt = (const float*)d_in[5];
    const float* lam1  = (const float*)d_in[6];
    const float* lam2  = (const float*)d_in[7];
    float* out = (float*)d_out;

    k_T<<<dim3(NS, NB, 2), 256>>>(F_src, F_tgt, lam1, lam2);
    k_asm<<<dim3(NN, NB), 256>>>(A_src, A_tgt, U_src, U_tgt, out);
}

// round 5
// speedup vs baseline: 2.1072x; 1.1594x over previous
#include <cuda_runtime.h>

#define NB 16     // batch
#define DD 128    // feature dim
#define NN 16     // nodes
#define EE 120    // candidate edges = 16*15/2
#define NS 4      // i-splits of the K reduction in k_T
#define IR 32     // rows per split (DD/NS)

// Partial bilinear forms: g_Tp[m][b][split][x*16+y]; k_asm sums over split.
__device__ float g_Tp[2][NB][NS][NN * NN];

// ---------------------------------------------------------------------------
// k_T: per (split s, batch b, matrix m) block computes V rows [32s,32s+32) of
//      V = relu(lam+lam^T) * Ft   and the partial  T_s = Fs_rows^T * V_rows.
// grid (4, 16, 2) = 128 blocks, 256 threads. All global loads coalesced;
// the lam transpose is done in shared memory (pad-33, conflict-free).
// ---------------------------------------------------------------------------
__global__ __launch_bounds__(256, 1)
void k_T(const float* __restrict__ F_src,
         const float* __restrict__ F_tgt,
         const float* __restrict__ lam1,
         const float* __restrict__ lam2) {
    __shared__ float sW[IR * DD];          // lam rows -> W in place (16 KB)
    __shared__ float sColT[DD * (IR + 1)]; // lam[:, ibase+c] padded (16.5 KB)
    __shared__ float sFt[DD * NN];         // 8 KB
    __shared__ float sFs[IR * NN];         // 2 KB
    __shared__ float sV[IR * NN];          // 2 KB

    const int s = blockIdx.x;
    const int b = blockIdx.y;
    const int m = blockIdx.z;
    const int t = threadIdx.x;
    const float* __restrict__ lam = (m == 0) ? lam1 : lam2;
    const int ibase = s * IR;

    // Let the dependent k_asm launch immediately (PDL overlap). No-op if
    // this kernel wasn't launched as a PDL primary.
    cudaTriggerProgrammaticLaunchCompletion();

    // --- coalesced staging ---------------------------------------------
    // lam rows [ibase, ibase+32) : 4096 floats
    #pragma unroll
    for (int k = 0; k < 16; k++) {
        int idx = t + k * 256;
        sW[idx] = lam[ibase * DD + idx];
    }
    // lam column slice lam[j][ibase+c] -> sColT[j*33 + c] : 4096 floats,
    // coalesced in 128B chunks (c consecutive in global memory).
    #pragma unroll
    for (int k = 0; k < 16; k++) {
        int idx = t + k * 256;
        int j = idx >> 5, c = idx & 31;
        sColT[j * (IR + 1) + c] = lam[j * DD + ibase + c];
    }
    // Ft full tile, Fs rows slice (coalesced)
    const float* __restrict__ Ft = F_tgt + b * DD * NN;
    #pragma unroll
    for (int k = 0; k < 8; k++)
        sFt[t + k * 256] = Ft[t + k * 256];
    {
        const float* __restrict__ Fs = F_src + b * DD * NN + ibase * NN;
        sFs[t]       = Fs[t];
        sFs[t + 256] = Fs[t + 256];
    }
    __syncthreads();

    // --- W = relu(row + col^T), in place; stride-33 reads conflict-free --
    #pragma unroll
    for (int k = 0; k < 16; k++) {
        int idx = t + k * 256;
        int il = idx >> 7, j = idx & 127;
        float v = sW[idx] + sColT[j * (IR + 1) + il];
        sW[idx] = v > 0.f ? v : 0.f;
    }
    __syncthreads();

    // --- V rows: thread t -> y = t&15, il in {t>>4, t>>4 + 16} ----------
    const int y  = t & 15;
    const int il = t >> 4;
    float a0 = 0.f, a1 = 0.f;
    #pragma unroll 8
    for (int j = 0; j < DD; j += 4) {
        float f0 = sFt[(j + 0) * NN + y];
        float f1 = sFt[(j + 1) * NN + y];
        float f2 = sFt[(j + 2) * NN + y];
        float f3 = sFt[(j + 3) * NN + y];
        float4 w0 = *reinterpret_cast<const float4*>(&sW[il * DD + j]);
        float4 w1 = *reinterpret_cast<const float4*>(&sW[(il + 16) * DD + j]);
        a0 += w0.x * f0 + w0.y * f1 + w0.z * f2 + w0.w * f3;
        a1 += w1.x * f0 + w1.y * f1 + w1.z * f2 + w1.w * f3;
    }
    sV[il * NN + y] = a0;
    sV[(il + 16) * NN + y] = a1;
    __syncthreads();

    // --- partial T over this i-slice: (x = t>>4, y = t&15) --------------
    const int x = t >> 4;
    float tv = 0.f;
    #pragma unroll
    for (int i = 0; i < IR; i++)
        tv += sFs[i * NN + x] * sV[i * NN + y];
    g_Tp[m][b][s][x * NN + y] = tv;
}

// ---------------------------------------------------------------------------
// k_asm: assemble M[b, i2*16+i1, j2*16+j1] for two i2 values per block.
// grid (8, 16) = 128 blocks (one wave), 256 threads, 8x STG.128 per thread.
// Preamble (A, U, Bm, Mp) runs before the PDL grid sync -> overlaps k_T.
// ---------------------------------------------------------------------------
__global__ __launch_bounds__(256, 1)
void k_asm(const int* __restrict__ A_src,
           const int* __restrict__ A_tgt,
           const float* __restrict__ U_src,
           const float* __restrict__ U_tgt,
           float* __restrict__ out) {
    __shared__ float T1[256];
    __shared__ float T2[256];
    __shared__ float sMp[32];             // Mp rows for the two i2 values
    __shared__ unsigned char Bm[EE + 8];

    const int i2base = blockIdx.x * 2;
    const int b      = blockIdx.y;
    const int t      = threadIdx.x;

    // ---- preamble: independent of k_T output ---------------------------
    if (t < EE)
        Bm[t] = (A_src[b * EE + t] > 0) && (A_tgt[b * EE + t] > 0);
    if (t < 32) {
        const int sel = t >> 4, mm = t & 15;
        const int i2v = i2base + sel;
        float sacc = 0.f;
        #pragma unroll
        for (int d = 0; d < 16; d++)
            sacc += U_src[(b * 16 + d) * 16 + i2v] * U_tgt[(b * 16 + d) * 16 + mm];
        sMp[t] = sacc;
    }

    // ---- wait for k_T (no-op if not a PDL launch) ----------------------
    cudaGridDependencySynchronize();

    // Sum the 4 K-split partials
    {
        float s1 = 0.f, s2 = 0.f;
        #pragma unroll
        for (int s = 0; s < NS; s++) {
            s1 += g_Tp[0][b][s][t];
            s2 += g_Tp[1][b][s][t];
        }
        T1[t] = s1;
        T2[t] = s2;
    }
    __syncthreads();

    // thread -> 4 consecutive j (one float4) x 4 i1 values, x 2 i2
    const int j4  = t & 63;          // j = 4*j4 .. 4*j4+3
    const int i1g = t >> 6;          // i1 = 4*i1g .. 4*i1g+3
    const int j2  = j4 >> 2;
    const int j1b = (j4 & 3) * 4;

    float t1j[4];                    // T1[j2, j1] per j1 lane (i2-independent)
    #pragma unroll
    for (int l = 0; l < 4; l++)
        t1j[l] = T1[j2 * 16 + j1b + l];

    #pragma unroll
    for (int sel = 0; sel < 2; sel++) {
        const int i2 = i2base + sel;
        const bool c2 = (i2 < j2);
        const int  e2 = c2 ? (i2 * (31 - i2)) / 2 + (j2 - i2 - 1) : 0;
        const bool b2 = c2 && (Bm[e2] != 0);
        const bool dg = (j2 == i2);

        float t2i[4];                // T2[i2, j1] per j1 lane
        #pragma unroll
        for (int l = 0; l < 4; l++)
            t2i[l] = T2[i2 * 16 + j1b + l];

        float* __restrict__ o =
            out + ((size_t)(b * 256 + i2 * 16 + i1g * 4)) * 256 + j2 * 16 + j1b;

        #pragma unroll
        for (int q = 0; q < 4; q++) {
            const int i1 = i1g * 4 + q;
            const float t1i = T1[i2 * 16 + i1];   // T1[i2, i1]
            const float t2j = T2[j2 * 16 + i1];   // T2[j2, i1]
            float4 v;
            float* vp = &v.x;
            #pragma unroll
            for (int l = 0; l < 4; l++) {
                const int j1 = j1b + l;
                float val = 0.f;
                if (b2 && i1 < j1) {
                    int e1 = (i1 * (31 - i1)) / 2 + (j1 - i1 - 1);
                    if (Bm[e1])
                        val = t1i + t2i[l] + t2j + t1j[l];
                }
                if (dg && j1 == i1) val += sMp[sel * 16 + i1];
                vp[l] = val;
            }
            *reinterpret_cast<float4*>(o + (size_t)q * 256) = v;
        }
    }
}

extern "C" void kernel_launch(void* const* d_in, const int* in_sizes, int n_in,
                              void* d_out, int out_size) {
    const int*   A_src = (const int*)d_in[0];
    const int*   A_tgt = (const int*)d_in[1];
    const float* F_src = (const float*)d_in[2];
    const float* F_tgt = (const float*)d_in[3];
    const float* U_src = (const float*)d_in[4];
    const float* U_tgt = (const float*)d_in[5];
    const float* lam1  = (const float*)d_in[6];
    const float* lam2  = (const float*)d_in[7];
    float* out = (float*)d_out;

    k_T<<<dim3(NS, NB, 2), 256>>>(F_src, F_tgt, lam1, lam2);

    // k_asm as PDL secondary: its preamble overlaps k_T.
    cudaLaunchConfig_t cfg = {};
    cfg.gridDim  = dim3(NN / 2, NB, 1);
    cfg.blockDim = dim3(256, 1, 1);
    cfg.dynamicSmemBytes = 0;
    cfg.stream = 0;
    cudaLaunchAttribute attr[1];
    attr[0].id = cudaLaunchAttributeProgrammaticStreamSerialization;
    attr[0].val.programmaticStreamSerializationAllowed = 1;
    cfg.attrs = attr;
    cfg.numAttrs = 1;

    cudaError_t e = cudaLaunchKernelEx(&cfg, k_asm, A_src, A_tgt, U_src, U_tgt, out);
    if (e != cudaSuccess) {
        // Fallback: plain ordered launch (gridsync is then a no-op).
        k_asm<<<dim3(NN / 2, NB), 256>>>(A_src, A_tgt, U_src, U_tgt, out);
    }
}

// round 6
// speedup vs baseline: 2.1701x; 1.0299x over previous
#include <cuda_runtime.h>

#define NB 16     // batch
#define DD 128    // feature dim
#define NN 16     // nodes
#define EE 120    // candidate edges = 16*15/2
#define NS 8      // i-splits of the K reduction (phase 1)
#define IR 16     // rows per split (DD/NS)
#define GRID 256  // NS*NB*2 phase-1 blocks == NN*NB phase-2 blocks

// Partial bilinear forms: g_Tp[m][b][split][x*16+y]
__device__ float g_Tp[2][NB][NS][NN * NN];
// Monotone device-wide barrier counter (+GRID per kernel invocation).
__device__ unsigned g_bar;

// ---------------------------------------------------------------------------
// Fused kernel, grid 256 x 256 threads, one wave (2 blocks/SM guaranteed).
// Phase 1 (block = (m, b, s)): V = relu(lam+lam^T)[rows] * Ft,
//                              T_s = Fs[rows]^T * V  -> g_Tp
// global spin barrier
// Phase 2 (block = (b2, i2)):  assemble M[b2, i2*16+i1, j]
// ---------------------------------------------------------------------------
__global__ __launch_bounds__(256, 2)
void k_fused(const int*   __restrict__ A_src,
             const int*   __restrict__ A_tgt,
             const float* __restrict__ F_src,
             const float* __restrict__ F_tgt,
             const float* __restrict__ U_src,
             const float* __restrict__ U_tgt,
             const float* __restrict__ lam1,
             const float* __restrict__ lam2,
             float*       __restrict__ out) {
    // phase-1 smem
    __shared__ float sW[IR * DD];            // 8 KB
    __shared__ float sColT[DD * (IR + 1)];   // 8.5 KB (pad 17, conflict-free)
    __shared__ float sFt[DD * NN];           // 8 KB
    __shared__ float sFs[IR * NN];           // 1 KB
    __shared__ float sV[IR * NN];            // 1 KB
    // phase-2 smem
    __shared__ float T1[256], T2[256];       // 2 KB
    __shared__ float sUs[16];
    __shared__ float sUt[256];               // 1 KB
    __shared__ float Mp[16];
    __shared__ unsigned char Bm[EE + 8];

    const int t   = threadIdx.x;
    const int bid = blockIdx.x;
    // phase-1 id: m in {0,1}, b in [0,16), s in [0,8)
    const int m = bid >> 7;
    const int b = (bid >> 3) & 15;
    const int s = bid & 7;
    // phase-2 id
    const int i2 = bid & 15;
    const int b2 = bid >> 4;

    // ======== phase-2 preamble (independent of phase 1; hides under it) ====
    if (t < EE)
        Bm[t] = (A_src[b2 * EE + t] > 0) && (A_tgt[b2 * EE + t] > 0);
    sUt[t] = U_tgt[b2 * 256 + t];
    if (t < 16)
        sUs[t] = U_src[b2 * 256 + t * 16 + i2];

    // ======== phase 1: staging (all coalesced, float4) =====================
    const float* __restrict__ lam = m ? lam2 : lam1;
    const int ibase = s * IR;
    {
        // lam rows [ibase, ibase+16) -> sW : 512 float4
        const float4* __restrict__ lr =
            reinterpret_cast<const float4*>(lam + ibase * DD);
        float4* __restrict__ wr = reinterpret_cast<float4*>(sW);
        wr[t]       = lr[t];
        wr[t + 256] = lr[t + 256];

        // lam column slice lam[j][ibase + c], c<16 -> sColT[j*17 + c]
        #pragma unroll
        for (int k = 0; k < 2; k++) {
            int idx4 = t + k * 256;            // 512 float4 total
            int j  = idx4 >> 2;
            int c4 = (idx4 & 3) * 4;
            float4 v = *reinterpret_cast<const float4*>(lam + j * DD + ibase + c4);
            float* dst = &sColT[j * (IR + 1) + c4];
            dst[0] = v.x; dst[1] = v.y; dst[2] = v.z; dst[3] = v.w;
        }
        // Ft full tile : 512 float4
        const float4* __restrict__ fr =
            reinterpret_cast<const float4*>(F_tgt + b * DD * NN);
        float4* __restrict__ fw = reinterpret_cast<float4*>(sFt);
        fw[t]       = fr[t];
        fw[t + 256] = fr[t + 256];
        // Fs rows slice : 64 float4
        if (t < 64) {
            reinterpret_cast<float4*>(sFs)[t] =
                reinterpret_cast<const float4*>(F_src + b * DD * NN + ibase * NN)[t];
        }
    }
    __syncthreads();

    // W = relu(row + col^T) in place
    #pragma unroll
    for (int k = 0; k < 8; k++) {
        int idx = t + k * 256;
        int il = idx >> 7, j = idx & 127;
        float v = sW[idx] + sColT[j * (IR + 1) + il];
        sW[idx] = v > 0.f ? v : 0.f;
    }
    __syncthreads();

    // V[il][y] = sum_j W[il][j] * Ft[j][y]   (one output per thread)
    const int y  = t & 15;
    const int il = t >> 4;
    {
        float a = 0.f;
        #pragma unroll 8
        for (int j = 0; j < DD; j += 4) {
            float4 w = *reinterpret_cast<const float4*>(&sW[il * DD + j]);
            a += w.x * sFt[(j + 0) * NN + y] + w.y * sFt[(j + 1) * NN + y]
               + w.z * sFt[(j + 2) * NN + y] + w.w * sFt[(j + 3) * NN + y];
        }
        sV[il * NN + y] = a;
    }
    __syncthreads();

    // partial T over this 16-row slice: (x = t>>4, y = t&15); t == x*16+y
    {
        const int x = t >> 4;
        float tv = 0.f;
        #pragma unroll
        for (int i = 0; i < IR; i++)
            tv += sFs[i * NN + x] * sV[i * NN + y];
        g_Tp[m][b][s][t] = tv;
    }

    // ======== device-wide barrier (release/acquire via g_bar) ==============
    __threadfence();          // make this thread's g_Tp store visible
    __syncthreads();          // all threads of block have fenced
    if (t == 0) {
        unsigned my = atomicAdd(&g_bar, 1u);
        unsigned target = (my / GRID) * GRID + GRID;   // base multiple of GRID
        while (*reinterpret_cast<volatile unsigned*>(&g_bar) < target) { }
    }
    __syncthreads();
    __threadfence();          // acquire

    // ======== phase 2 ======================================================
    {
        float s1 = 0.f, s2 = 0.f;
        #pragma unroll
        for (int ss = 0; ss < NS; ss++) {
            s1 += __ldcg(&g_Tp[0][b2][ss][t]);
            s2 += __ldcg(&g_Tp[1][b2][ss][t]);
        }
        T1[t] = s1;
        T2[t] = s2;
    }
    if (t < 16) {
        float acc = 0.f;
        #pragma unroll
        for (int d = 0; d < 16; d++)
            acc += sUs[d] * sUt[d * 16 + t];
        Mp[t] = acc;
    }
    __syncthreads();

    // thread -> 4 consecutive j (one float4) x 4 i1 values, single i2
    const int j4  = t & 63;          // j = 4*j4 .. 4*j4+3
    const int i1g = t >> 6;          // i1 = 4*i1g .. 4*i1g+3
    const int j2  = j4 >> 2;
    const int j1b = (j4 & 3) * 4;

    const bool c2 = (i2 < j2);
    const int  e2 = c2 ? (i2 * (31 - i2)) / 2 + (j2 - i2 - 1) : 0;
    const bool b2e = c2 && (Bm[e2] != 0);
    const bool dg = (j2 == i2);

    float t2i[4], t1j[4];            // T2[i2, j1], T1[j2, j1] per j1 lane
    #pragma unroll
    for (int l = 0; l < 4; l++) {
        t2i[l] = T2[i2 * 16 + j1b + l];
        t1j[l] = T1[j2 * 16 + j1b + l];
    }

    float* __restrict__ o =
        out + ((size_t)(b2 * 256 + i2 * 16 + i1g * 4)) * 256 + j2 * 16 + j1b;

    #pragma unroll
    for (int q = 0; q < 4; q++) {
        const int i1 = i1g * 4 + q;
        const float t1i = T1[i2 * 16 + i1];   // T1[i2, i1]
        const float t2j = T2[j2 * 16 + i1];   // T2[j2, i1]
        float4 v;
        float* vp = &v.x;
        #pragma unroll
        for (int l = 0; l < 4; l++) {
            const int j1 = j1b + l;
            float val = 0.f;
            if (b2e && i1 < j1) {
                int e1 = (i1 * (31 - i1)) / 2 + (j1 - i1 - 1);
                if (Bm[e1])
                    val = t1i + t2i[l] + t2j + t1j[l];
            }
            if (dg && j1 == i1) val += Mp[i1];
            vp[l] = val;
        }
        *reinterpret_cast<float4*>(o + (size_t)q * 256) = v;
    }
}

extern "C" void kernel_launch(void* const* d_in, const int* in_sizes, int n_in,
                              void* d_out, int out_size) {
    const int*   A_src = (const int*)d_in[0];
    const int*   A_tgt = (const int*)d_in[1];
    const float* F_src = (const float*)d_in[2];
    const float* F_tgt = (const float*)d_in[3];
    const float* U_src = (const float*)d_in[4];
    const float* U_tgt = (const float*)d_in[5];
    const float* lam1  = (const float*)d_in[6];
    const float* lam2  = (const float*)d_in[7];
    float* out = (float*)d_out;

    k_fused<<<GRID, 256>>>(A_src, A_tgt, F_src, F_tgt,
                           U_src, U_tgt, lam1, lam2, out);
}